// round 3
// baseline (speedup 1.0000x reference)
#include <cuda_runtime.h>
#include <cstdint>

#define NMAX 100000
#define EMAX 1600000
#define DH   128

// ---------------- scratch (device globals; no allocs allowed) ----------------
__device__ float g_h[(size_t)NMAX * DH];     // GEMM output
__device__ float g_agg[(size_t)NMAX * DH];   // neighborhood aggregation
__device__ float g_act[(size_t)NMAX * DH];   // layer-0 activations
__device__ float g_deg[NMAX];
__device__ float g_dinv[NMAX];
__device__ int   g_src[EMAX];
__device__ int   g_dst[EMAX];
__device__ int   g_is64;

// ---------------- index dtype detection + conversion ----------------

// The reference declares edge_index as int64, but JAX silently downcasts to
// int32 unless x64 is enabled. Detect which layout the buffer actually has:
// read the first 64 words as int64 — int32 data has nonzero high words.
__global__ void detect_kernel(const long long* __restrict__ ei, int E, int n) {
    if (threadIdx.x == 0 && blockIdx.x == 0) {
        int probes = E < 64 ? E : 64;
        int is64 = 1;
        for (int i = 0; i < probes; i++) {
            long long v = ei[i];
            if (v < 0 || v >= (long long)n) { is64 = 0; break; }
        }
        g_is64 = is64;
    }
}

__global__ void convert_kernel(const void* __restrict__ ei, int E) {
    int e = blockIdx.x * blockDim.x + threadIdx.x;
    if (e >= E) return;
    if (g_is64) {
        const long long* p = (const long long*)ei;
        g_src[e] = (int)p[e];
        g_dst[e] = (int)p[(size_t)E + e];
    } else {
        const int* p = (const int*)ei;
        g_src[e] = p[e];
        g_dst[e] = p[(size_t)E + e];
    }
}

// ---------------- kernels ----------------

__global__ void zero_agg_kernel(int n4) {
    int i = blockIdx.x * blockDim.x + threadIdx.x;
    if (i < n4) ((float4*)g_agg)[i] = make_float4(0.f, 0.f, 0.f, 0.f);
}

__global__ void zero_deg_kernel(int n) {
    int i = blockIdx.x * blockDim.x + threadIdx.x;
    if (i < n) g_deg[i] = 0.f;
}

__global__ void deg_kernel(int E) {
    int e = blockIdx.x * blockDim.x + threadIdx.x;
    if (e >= E) return;
    atomicAdd(&g_deg[g_dst[e]], 1.0f);
}

__global__ void dinv_kernel(int n) {
    int i = blockIdx.x * blockDim.x + threadIdx.x;
    if (i < n) g_dinv[i] = rsqrtf(g_deg[i] + 1.0f);
}

// Tiled SIMT fp32 GEMM: g_h[N,128] = x[N,128] @ W[128,128]
// 256 threads, 64 rows/block. Static smem = 32KB x-tile + 16KB W-chunk = 48KB.
// K is processed in 4 chunks of 32. Thread (wg=tid/32, lane=tid%32) computes
// rows wg*8..+7, cols lane*4..+3. sX reads are warp-broadcast; sW reads are
// 512B/warp conflict-free.
__global__ __launch_bounds__(256) void gemm_kernel(
    const float* __restrict__ x, const float* __restrict__ W,
    int nrows, int use_act)
{
    __shared__ float sX[64 * DH];   // 32 KB
    __shared__ float sW[32 * DH];   // 16 KB

    int tid = threadIdx.x;
    int row0 = blockIdx.x * 64;
    const float4* x4 = use_act ? (const float4*)g_act : (const float4*)x;
    float4* sX4 = (float4*)sX;
#pragma unroll
    for (int i = 0; i < 8; i++) {
        int idx = tid + i * 256;          // 0..2047 (64 rows x 32 float4)
        int r = idx >> 5, c = idx & 31;
        sX4[idx] = (row0 + r < nrows) ? x4[(size_t)(row0 + r) * 32 + c]
                                      : make_float4(0.f, 0.f, 0.f, 0.f);
    }

    int lane = tid & 31;   // col group
    int wg   = tid >> 5;   // row group
    float acc[8][4];
#pragma unroll
    for (int r = 0; r < 8; r++)
#pragma unroll
        for (int c = 0; c < 4; c++) acc[r][c] = 0.f;

    const float* xs = sX + wg * 8 * DH;
    const float4* W4 = (const float4*)W;
    float4* sW4 = (float4*)sW;

    for (int kc = 0; kc < 4; kc++) {
        __syncthreads();
        // load W rows [kc*32, kc*32+32) : 32*128 floats = 1024 float4
#pragma unroll
        for (int i = 0; i < 4; i++)
            sW4[tid + i * 256] = W4[kc * 1024 + tid + i * 256];
        __syncthreads();

#pragma unroll 8
        for (int k = 0; k < 32; k++) {
            float4 w = sW4[k * 32 + lane];
#pragma unroll
            for (int r = 0; r < 8; r++) {
                float xv = xs[r * DH + kc * 32 + k];
                acc[r][0] += xv * w.x;
                acc[r][1] += xv * w.y;
                acc[r][2] += xv * w.z;
                acc[r][3] += xv * w.w;
            }
        }
    }

#pragma unroll
    for (int r = 0; r < 8; r++) {
        int row = row0 + wg * 8 + r;
        if (row < nrows)
            ((float4*)(g_h + (size_t)row * DH))[lane] =
                make_float4(acc[r][0], acc[r][1], acc[r][2], acc[r][3]);
    }
}

// One warp per edge; each lane handles one float4 of the 128-dim message.
// g_agg[dst] += g_h[src] * dinv[src]*dinv[dst], scalar return-less atomics (REDG).
__global__ void edge_agg_kernel(int E) {
    int t = blockIdx.x * blockDim.x + threadIdx.x;
    int e = t >> 5;
    if (e >= E) return;
    int lane = t & 31;
    int src = g_src[e];
    int dst = g_dst[e];
    float norm = g_dinv[src] * g_dinv[dst];
    float4 v = ((const float4*)g_h)[(size_t)src * 32 + lane];
    float* a = g_agg + (size_t)dst * DH + lane * 4;
    atomicAdd(a + 0, v.x * norm);
    atomicAdd(a + 1, v.y * norm);
    atomicAdd(a + 2, v.z * norm);
    atomicAdd(a + 3, v.w * norm);
}

// dst = g_agg + g_h * dinv^2 (self-loop) + bias, optional ReLU.
// Writes g_act (to_act=1) or out (to_act=0).
__global__ void combine_kernel(const float4* __restrict__ bias,
                               float4* __restrict__ out, int n,
                               int do_relu, int to_act)
{
    int t = blockIdx.x * blockDim.x + threadIdx.x;  // over n*32 float4s
    if (t >= n * 32) return;
    int row = t >> 5, c = t & 31;
    float d = g_dinv[row];
    float d2 = d * d;
    float4 a = ((const float4*)g_agg)[t];
    float4 hv = ((const float4*)g_h)[t];
    float4 b = bias[c];
    float4 v = make_float4(a.x + hv.x * d2 + b.x,
                           a.y + hv.y * d2 + b.y,
                           a.z + hv.z * d2 + b.z,
                           a.w + hv.w * d2 + b.w);
    if (do_relu) {
        v.x = fmaxf(v.x, 0.f); v.y = fmaxf(v.y, 0.f);
        v.z = fmaxf(v.z, 0.f); v.w = fmaxf(v.w, 0.f);
    }
    float4* dst4 = to_act ? (float4*)g_act : out;
    dst4[t] = v;
}

// ---------------- host orchestration ----------------

static void run_graph(const float* x, const void* ei, int n, int E,
                      const float* W0, const float* b0,
                      const float* W1, const float* b1,
                      float* out)
{
    const int TPB = 256;
    int nfeat4 = n * (DH / 4);
    int gemm_blocks = (n + 63) / 64;
    int edge_blocks = (E * 32 + TPB - 1) / TPB;

    // index conversion + degree + normalization
    detect_kernel<<<1, 1>>>((const long long*)ei, E, n);
    convert_kernel<<<(E + TPB - 1) / TPB, TPB>>>(ei, E);
    zero_deg_kernel<<<(n + TPB - 1) / TPB, TPB>>>(n);
    deg_kernel<<<(E + TPB - 1) / TPB, TPB>>>(E);
    dinv_kernel<<<(n + TPB - 1) / TPB, TPB>>>(n);

    // layer 0
    gemm_kernel<<<gemm_blocks, TPB>>>(x, W0, n, 0);
    zero_agg_kernel<<<(nfeat4 + TPB - 1) / TPB, TPB>>>(nfeat4);
    edge_agg_kernel<<<edge_blocks, TPB>>>(E);
    combine_kernel<<<(n * 32 + TPB - 1) / TPB, TPB>>>(
        (const float4*)b0, nullptr, n, 1, 1);

    // layer 1
    gemm_kernel<<<gemm_blocks, TPB>>>(nullptr, W1, n, 1);
    zero_agg_kernel<<<(nfeat4 + TPB - 1) / TPB, TPB>>>(nfeat4);
    edge_agg_kernel<<<edge_blocks, TPB>>>(E);
    combine_kernel<<<(n * 32 + TPB - 1) / TPB, TPB>>>(
        (const float4*)b1, (float4*)out, n, 0, 0);
}

extern "C" void kernel_launch(void* const* d_in, const int* in_sizes, int n_in,
                              void* d_out, int out_size)
{
    const float* x1  = (const float*)d_in[0];
    const void*  ei1 = d_in[1];
    const float* x2  = (const float*)d_in[2];
    const void*  ei2 = d_in[3];
    const float* W0  = (const float*)d_in[4];
    const float* b0  = (const float*)d_in[5];
    const float* W1  = (const float*)d_in[6];
    const float* b1  = (const float*)d_in[7];
    float* out = (float*)d_out;

    int n  = in_sizes[0] / DH;      // 100000
    int E1 = in_sizes[1] / 2;       // 1600000
    int E2 = in_sizes[3] / 2;

    run_graph(x1, ei1, n, E1, W0, b0, W1, b1, out);
    run_graph(x2, ei2, n, E2, W0, b0, W1, b1, out + (size_t)n * DH);
}

// round 4
// speedup vs baseline: 3.0878x; 3.0878x over previous
#include <cuda_runtime.h>
#include <cstdint>

#define NMAX 100000
#define EMAX 1600000
#define DH   128
#define SCAN_B 1024

// ---------------- scratch (device globals; no allocs allowed) ----------------
__device__ float g_h[(size_t)NMAX * DH];     // GEMM output
__device__ float g_act[(size_t)NMAX * DH];   // layer-0 activations
__device__ float g_dinv[NMAX];
__device__ int   g_src[EMAX];
__device__ int   g_dst[EMAX];
__device__ int   g_cnt[NMAX];                // degree histogram, then scatter cursor
__device__ int   g_rowptr[NMAX + 1];
__device__ int2  g_csr[EMAX];                // {src, float bits of norm}, dst-sorted
__device__ int   g_bsum[256];                // scan block sums
__device__ int   g_is64;

// ---------------- index dtype detection + conversion ----------------
// Reference declares int64 edge_index, but JAX silently downcasts to int32
// unless x64 is enabled. Probe the first words read as int64.
__global__ void detect_kernel(const long long* __restrict__ ei, int E, int n) {
    if (threadIdx.x == 0 && blockIdx.x == 0) {
        int probes = E < 64 ? E : 64;
        int is64 = 1;
        for (int i = 0; i < probes; i++) {
            long long v = ei[i];
            if (v < 0 || v >= (long long)n) { is64 = 0; break; }
        }
        g_is64 = is64;
    }
}

__global__ void convert_kernel(const void* __restrict__ ei, int E) {
    int e = blockIdx.x * blockDim.x + threadIdx.x;
    if (e >= E) return;
    if (g_is64) {
        const long long* p = (const long long*)ei;
        g_src[e] = (int)p[e];
        g_dst[e] = (int)p[(size_t)E + e];
    } else {
        const int* p = (const int*)ei;
        g_src[e] = p[e];
        g_dst[e] = p[(size_t)E + e];
    }
}

// ---------------- CSR build ----------------

__global__ void zero_cnt_kernel(int n) {
    int i = blockIdx.x * blockDim.x + threadIdx.x;
    if (i < n) g_cnt[i] = 0;
}

__global__ void count_kernel(int E) {
    int e = blockIdx.x * blockDim.x + threadIdx.x;
    if (e >= E) return;
    atomicAdd(&g_cnt[g_dst[e]], 1);
}

__global__ void dinv_kernel(int n) {
    int i = blockIdx.x * blockDim.x + threadIdx.x;
    if (i < n) g_dinv[i] = rsqrtf((float)g_cnt[i] + 1.0f);
}

// exclusive scan of g_cnt into g_rowptr, two-level
__global__ void scan_block_kernel(int n) {
    __shared__ int s[SCAN_B];
    int gid = blockIdx.x * SCAN_B + threadIdx.x;
    int v = (gid < n) ? g_cnt[gid] : 0;
    s[threadIdx.x] = v;
    __syncthreads();
#pragma unroll
    for (int off = 1; off < SCAN_B; off <<= 1) {
        int t = (threadIdx.x >= off) ? s[threadIdx.x - off] : 0;
        __syncthreads();
        s[threadIdx.x] += t;
        __syncthreads();
    }
    if (gid < n) g_rowptr[gid] = s[threadIdx.x] - v;   // exclusive
    if (threadIdx.x == SCAN_B - 1) g_bsum[blockIdx.x] = s[SCAN_B - 1];
}

__global__ void scan_top_kernel(int nb, int n, int E) {
    __shared__ int s[256];
    int v = (threadIdx.x < nb) ? g_bsum[threadIdx.x] : 0;
    s[threadIdx.x] = v;
    __syncthreads();
#pragma unroll
    for (int off = 1; off < 256; off <<= 1) {
        int t = (threadIdx.x >= off) ? s[threadIdx.x - off] : 0;
        __syncthreads();
        s[threadIdx.x] += t;
        __syncthreads();
    }
    if (threadIdx.x < nb) g_bsum[threadIdx.x] = s[threadIdx.x] - v;  // exclusive
    if (threadIdx.x == 0) g_rowptr[n] = E;
}

__global__ void scan_add_kernel(int n) {
    int gid = blockIdx.x * blockDim.x + threadIdx.x;
    if (gid < n) g_rowptr[gid] += g_bsum[gid / SCAN_B];
}

__global__ void fill_kernel(int E) {
    int e = blockIdx.x * blockDim.x + threadIdx.x;
    if (e >= E) return;
    int src = g_src[e], dst = g_dst[e];
    int pos = g_rowptr[dst] + atomicAdd(&g_cnt[dst], 1);
    float norm = g_dinv[src] * g_dinv[dst];
    g_csr[pos] = make_int2(src, __float_as_int(norm));
}

// ---------------- GEMM ----------------
// g_h[N,128] = x[N,128] @ W[128,128]; 256 threads, 64 rows/block,
// static smem 48KB, K chunked x4.
__global__ __launch_bounds__(256) void gemm_kernel(
    const float* __restrict__ x, const float* __restrict__ W,
    int nrows, int use_act)
{
    __shared__ float sX[64 * DH];   // 32 KB
    __shared__ float sW[32 * DH];   // 16 KB

    int tid = threadIdx.x;
    int row0 = blockIdx.x * 64;
    const float4* x4 = use_act ? (const float4*)g_act : (const float4*)x;
    float4* sX4 = (float4*)sX;
#pragma unroll
    for (int i = 0; i < 8; i++) {
        int idx = tid + i * 256;
        int r = idx >> 5, c = idx & 31;
        sX4[idx] = (row0 + r < nrows) ? x4[(size_t)(row0 + r) * 32 + c]
                                      : make_float4(0.f, 0.f, 0.f, 0.f);
    }

    int lane = tid & 31;
    int wg   = tid >> 5;
    float acc[8][4];
#pragma unroll
    for (int r = 0; r < 8; r++)
#pragma unroll
        for (int c = 0; c < 4; c++) acc[r][c] = 0.f;

    const float* xs = sX + wg * 8 * DH;
    const float4* W4 = (const float4*)W;
    float4* sW4 = (float4*)sW;

    for (int kc = 0; kc < 4; kc++) {
        __syncthreads();
#pragma unroll
        for (int i = 0; i < 4; i++)
            sW4[tid + i * 256] = W4[kc * 1024 + tid + i * 256];
        __syncthreads();

#pragma unroll 8
        for (int k = 0; k < 32; k++) {
            float4 w = sW4[k * 32 + lane];
#pragma unroll
            for (int r = 0; r < 8; r++) {
                float xv = xs[r * DH + kc * 32 + k];
                acc[r][0] += xv * w.x;
                acc[r][1] += xv * w.y;
                acc[r][2] += xv * w.z;
                acc[r][3] += xv * w.w;
            }
        }
    }

#pragma unroll
    for (int r = 0; r < 8; r++) {
        int row = row0 + wg * 8 + r;
        if (row < nrows)
            ((float4*)(g_h + (size_t)row * DH))[lane] =
                make_float4(acc[r][0], acc[r][1], acc[r][2], acc[r][3]);
    }
}

// ---------------- fused gather + combine ----------------
// One warp per dst node. Lane owns one float4 column chunk. Accumulates all
// in-edges (CSR gather, no atomics), adds self-loop + bias, optional ReLU,
// writes result once.
__global__ void gather_kernel(const float4* __restrict__ bias,
                              float4* __restrict__ out, int n,
                              int do_relu, int to_act)
{
    int t = blockIdx.x * blockDim.x + threadIdx.x;
    int node = t >> 5;
    if (node >= n) return;
    int lane = t & 31;

    int beg = g_rowptr[node];
    int end = g_rowptr[node + 1];

    float4 acc = make_float4(0.f, 0.f, 0.f, 0.f);
    const float4* h4 = (const float4*)g_h;
    for (int j = beg; j < end; j++) {
        int2 e = g_csr[j];
        float nrm = __int_as_float(e.y);
        float4 v = h4[(size_t)e.x * 32 + lane];
        acc.x += v.x * nrm;
        acc.y += v.y * nrm;
        acc.z += v.z * nrm;
        acc.w += v.w * nrm;
    }

    float d = g_dinv[node];
    float d2 = d * d;
    float4 hv = h4[(size_t)node * 32 + lane];
    float4 b = bias[lane];
    float4 v = make_float4(acc.x + hv.x * d2 + b.x,
                           acc.y + hv.y * d2 + b.y,
                           acc.z + hv.z * d2 + b.z,
                           acc.w + hv.w * d2 + b.w);
    if (do_relu) {
        v.x = fmaxf(v.x, 0.f); v.y = fmaxf(v.y, 0.f);
        v.z = fmaxf(v.z, 0.f); v.w = fmaxf(v.w, 0.f);
    }
    float4* dst4 = to_act ? (float4*)g_act : out;
    dst4[(size_t)node * 32 + lane] = v;
}

// ---------------- host orchestration ----------------

static void run_graph(const float* x, const void* ei, int n, int E,
                      const float* W0, const float* b0,
                      const float* W1, const float* b1,
                      float* out)
{
    const int TPB = 256;
    int gemm_blocks = (n + 63) / 64;
    int node_blocks = (n + TPB - 1) / TPB;
    int edge_blocks = (E + TPB - 1) / TPB;
    int warp_blocks = (n * 32 + TPB - 1) / TPB;
    int scan_blocks = (n + SCAN_B - 1) / SCAN_B;

    // ---- CSR build (once per graph, reused by both layers) ----
    detect_kernel<<<1, 1>>>((const long long*)ei, E, n);
    convert_kernel<<<edge_blocks, TPB>>>(ei, E);
    zero_cnt_kernel<<<node_blocks, TPB>>>(n);
    count_kernel<<<edge_blocks, TPB>>>(E);
    dinv_kernel<<<node_blocks, TPB>>>(n);
    scan_block_kernel<<<scan_blocks, SCAN_B>>>(n);
    scan_top_kernel<<<1, 256>>>(scan_blocks, n, E);
    scan_add_kernel<<<node_blocks, TPB>>>(n);
    zero_cnt_kernel<<<node_blocks, TPB>>>(n);
    fill_kernel<<<edge_blocks, TPB>>>(E);

    // ---- layer 0 ----
    gemm_kernel<<<gemm_blocks, TPB>>>(x, W0, n, 0);
    gather_kernel<<<warp_blocks, TPB>>>((const float4*)b0, nullptr, n, 1, 1);

    // ---- layer 1 ----
    gemm_kernel<<<gemm_blocks, TPB>>>(nullptr, W1, n, 1);
    gather_kernel<<<warp_blocks, TPB>>>((const float4*)b1, (float4*)out, n, 0, 0);
}

extern "C" void kernel_launch(void* const* d_in, const int* in_sizes, int n_in,
                              void* d_out, int out_size)
{
    const float* x1  = (const float*)d_in[0];
    const void*  ei1 = d_in[1];
    const float* x2  = (const float*)d_in[2];
    const void*  ei2 = d_in[3];
    const float* W0  = (const float*)d_in[4];
    const float* b0  = (const float*)d_in[5];
    const float* W1  = (const float*)d_in[6];
    const float* b1  = (const float*)d_in[7];
    float* out = (float*)d_out;

    int n  = in_sizes[0] / DH;      // 100000
    int E1 = in_sizes[1] / 2;       // 1600000
    int E2 = in_sizes[3] / 2;

    run_graph(x1, ei1, n, E1, W0, b0, W1, b1, out);
    run_graph(x2, ei2, n, E2, W0, b0, W1, b1, out + (size_t)n * DH);
}

// round 5
// speedup vs baseline: 4.2653x; 1.3813x over previous
#include <cuda_runtime.h>
#include <cstdint>

#define NMAX 100000
#define EMAX 1600000
#define DH   128
#define SCAN_B 1024
#define XS 36    // sX row stride (floats), padded: conflict-free A-fragment LDS
#define WS 132   // sW row stride (floats), padded: conflict-free B-fragment LDS

// ---------------- scratch (device globals; no allocs allowed) ----------------
__device__ float g_h[(size_t)NMAX * DH];     // GEMM output
__device__ float g_act[(size_t)NMAX * DH];   // layer-0 activations
__device__ float g_dinv[NMAX];
__device__ int   g_cnt[NMAX];                // degree histogram, then scatter cursor
__device__ int   g_rowptr[NMAX + 1];
__device__ int2  g_csr[EMAX];                // {src, float bits of norm}, dst-sorted
__device__ int   g_bsum[256];                // scan block sums
__device__ int   g_is64;

// ---------------- index dtype detection ----------------
// Reference declares int64 edge_index, but JAX silently downcasts to int32
// unless x64 is enabled. Probe the first words read as int64.
__global__ void detect_kernel(const long long* __restrict__ ei, int E, int n) {
    if (threadIdx.x == 0 && blockIdx.x == 0) {
        int probes = E < 64 ? E : 64;
        int is64 = 1;
        for (int i = 0; i < probes; i++) {
            long long v = ei[i];
            if (v < 0 || v >= (long long)n) { is64 = 0; break; }
        }
        g_is64 = is64;
    }
}

__device__ __forceinline__ int load_src(const void* ei, int E, int e) {
    return g_is64 ? (int)((const long long*)ei)[e] : ((const int*)ei)[e];
}
__device__ __forceinline__ int load_dst(const void* ei, int E, int e) {
    return g_is64 ? (int)((const long long*)ei)[(size_t)E + e]
                  : ((const int*)ei)[(size_t)E + e];
}

// ---------------- CSR build ----------------

__global__ void zero_cnt_kernel(int n) {
    int i = blockIdx.x * blockDim.x + threadIdx.x;
    if (i < n) g_cnt[i] = 0;
}

__global__ void count_kernel(const void* __restrict__ ei, int E) {
    int e = blockIdx.x * blockDim.x + threadIdx.x;
    if (e >= E) return;
    atomicAdd(&g_cnt[load_dst(ei, E, e)], 1);
}

__global__ void dinv_kernel(int n) {
    int i = blockIdx.x * blockDim.x + threadIdx.x;
    if (i < n) g_dinv[i] = rsqrtf((float)g_cnt[i] + 1.0f);
}

// exclusive scan of g_cnt into g_rowptr, two-level
__global__ void scan_block_kernel(int n) {
    __shared__ int s[SCAN_B];
    int gid = blockIdx.x * SCAN_B + threadIdx.x;
    int v = (gid < n) ? g_cnt[gid] : 0;
    s[threadIdx.x] = v;
    __syncthreads();
#pragma unroll
    for (int off = 1; off < SCAN_B; off <<= 1) {
        int t = (threadIdx.x >= off) ? s[threadIdx.x - off] : 0;
        __syncthreads();
        s[threadIdx.x] += t;
        __syncthreads();
    }
    if (gid < n) g_rowptr[gid] = s[threadIdx.x] - v;   // exclusive
    if (threadIdx.x == SCAN_B - 1) g_bsum[blockIdx.x] = s[SCAN_B - 1];
}

__global__ void scan_top_kernel(int nb, int n, int E) {
    __shared__ int s[256];
    int v = (threadIdx.x < nb) ? g_bsum[threadIdx.x] : 0;
    s[threadIdx.x] = v;
    __syncthreads();
#pragma unroll
    for (int off = 1; off < 256; off <<= 1) {
        int t = (threadIdx.x >= off) ? s[threadIdx.x - off] : 0;
        __syncthreads();
        s[threadIdx.x] += t;
        __syncthreads();
    }
    if (threadIdx.x < nb) g_bsum[threadIdx.x] = s[threadIdx.x] - v;  // exclusive
    if (threadIdx.x == 0) g_rowptr[n] = E;
}

__global__ void scan_add_kernel(int n) {
    int gid = blockIdx.x * blockDim.x + threadIdx.x;
    if (gid < n) g_rowptr[gid] += g_bsum[gid / SCAN_B];
}

__global__ void fill_kernel(const void* __restrict__ ei, int E) {
    int e = blockIdx.x * blockDim.x + threadIdx.x;
    if (e >= E) return;
    int src = load_src(ei, E, e);
    int dst = load_dst(ei, E, e);
    int pos = g_rowptr[dst] + atomicAdd(&g_cnt[dst], 1);
    float norm = g_dinv[src] * g_dinv[dst];
    g_csr[pos] = make_int2(src, __float_as_int(norm));
}

// ---------------- tensor-core TF32 GEMM ----------------
// g_h[N,128] = x[N,128] @ W[128,128]
// 128 rows/block, 8 warps; warp tile 32x64 = 2x8 m16n8k8 tiles; K chunked x32.
// fp32 -> tf32 conversion happens at the global->smem copy (inner loop is pure
// LDS + HMMA). Padded smem strides make all fragment loads conflict-free.

__device__ __forceinline__ uint32_t f2tf(float f) {
    uint32_t u;
    asm("cvt.rna.tf32.f32 %0, %1;" : "=r"(u) : "f"(f));
    return u;
}

__global__ __launch_bounds__(256) void gemm_tc_kernel(
    const float* __restrict__ x, const float* __restrict__ W,
    int nrows, int use_act)
{
    __shared__ uint32_t sX[128 * XS];   // 18432 B
    __shared__ uint32_t sW[32 * WS];    // 16896 B

    int tid = threadIdx.x;
    int lane = tid & 31;
    int w = tid >> 5;
    int row0 = blockIdx.x * 128;
    int mrow0 = (w & 3) * 32;
    int ncol0 = (w >> 2) * 64;
    int gi = lane >> 2;   // groupID
    int ti = lane & 3;    // thread-in-group

    const float4* xp4 = use_act ? (const float4*)g_act : (const float4*)x;
    const float4* W4 = (const float4*)W;

    float c[2][8][4];
#pragma unroll
    for (int m = 0; m < 2; m++)
#pragma unroll
        for (int nt = 0; nt < 8; nt++)
#pragma unroll
            for (int i = 0; i < 4; i++) c[m][nt][i] = 0.f;

    for (int kc = 0; kc < 4; kc++) {
        __syncthreads();
        // x tile: rows row0..+127, cols kc*32..+31  (1024 float4, 4/thread)
#pragma unroll
        for (int i = 0; i < 4; i++) {
            int idx = tid + i * 256;
            int r = idx >> 3, c4 = idx & 7;
            float4 v = (row0 + r < nrows)
                ? xp4[(size_t)(row0 + r) * 32 + kc * 8 + c4]
                : make_float4(0.f, 0.f, 0.f, 0.f);
            uint32_t* d = &sX[r * XS + c4 * 4];
            d[0] = f2tf(v.x); d[1] = f2tf(v.y); d[2] = f2tf(v.z); d[3] = f2tf(v.w);
        }
        // W tile: rows kc*32..+31, all 128 cols  (1024 float4, 4/thread)
#pragma unroll
        for (int i = 0; i < 4; i++) {
            int idx = tid + i * 256;
            int r = idx >> 5, c4 = idx & 31;
            float4 v = W4[(size_t)(kc * 32 + r) * 32 + c4];
            uint32_t* d = &sW[r * WS + c4 * 4];
            d[0] = f2tf(v.x); d[1] = f2tf(v.y); d[2] = f2tf(v.z); d[3] = f2tf(v.w);
        }
        __syncthreads();

#pragma unroll
        for (int kk = 0; kk < 4; kk++) {
            int kcol = kk * 8;
            uint32_t a[2][4];
#pragma unroll
            for (int m = 0; m < 2; m++) {
                int rb = mrow0 + m * 16 + gi;
                a[m][0] = sX[rb * XS + kcol + ti];
                a[m][1] = sX[(rb + 8) * XS + kcol + ti];
                a[m][2] = sX[rb * XS + kcol + ti + 4];
                a[m][3] = sX[(rb + 8) * XS + kcol + ti + 4];
            }
#pragma unroll
            for (int nt = 0; nt < 8; nt++) {
                int n0 = ncol0 + nt * 8 + gi;
                uint32_t b0 = sW[(kcol + ti) * WS + n0];
                uint32_t b1 = sW[(kcol + ti + 4) * WS + n0];
#pragma unroll
                for (int m = 0; m < 2; m++) {
                    asm volatile(
                        "mma.sync.aligned.m16n8k8.row.col.f32.tf32.tf32.f32 "
                        "{%0,%1,%2,%3}, {%4,%5,%6,%7}, {%8,%9}, {%0,%1,%2,%3};"
                        : "+f"(c[m][nt][0]), "+f"(c[m][nt][1]),
                          "+f"(c[m][nt][2]), "+f"(c[m][nt][3])
                        : "r"(a[m][0]), "r"(a[m][1]), "r"(a[m][2]), "r"(a[m][3]),
                          "r"(b0), "r"(b1));
                }
            }
        }
    }

    // epilogue: c0/c1 -> row gi, cols 2ti,2ti+1 ; c2/c3 -> row gi+8
#pragma unroll
    for (int m = 0; m < 2; m++) {
        int r0 = row0 + mrow0 + m * 16 + gi;
#pragma unroll
        for (int nt = 0; nt < 8; nt++) {
            int col = ncol0 + nt * 8 + 2 * ti;
            if (r0 < nrows)
                *(float2*)&g_h[(size_t)r0 * DH + col] =
                    make_float2(c[m][nt][0], c[m][nt][1]);
            if (r0 + 8 < nrows)
                *(float2*)&g_h[(size_t)(r0 + 8) * DH + col] =
                    make_float2(c[m][nt][2], c[m][nt][3]);
        }
    }
}

// ---------------- fused gather + combine ----------------
// One warp per dst node. Lane owns one float4 column chunk. Accumulates all
// in-edges (CSR gather, no atomics), adds self-loop + bias, optional ReLU,
// writes result once.
__global__ void gather_kernel(const float4* __restrict__ bias,
                              float4* __restrict__ out, int n,
                              int do_relu, int to_act)
{
    int t = blockIdx.x * blockDim.x + threadIdx.x;
    int node = t >> 5;
    if (node >= n) return;
    int lane = t & 31;

    int beg = g_rowptr[node];
    int end = g_rowptr[node + 1];

    float4 acc = make_float4(0.f, 0.f, 0.f, 0.f);
    const float4* h4 = (const float4*)g_h;
    int j = beg;
    for (; j + 1 < end; j += 2) {
        int2 e0 = g_csr[j];
        int2 e1 = g_csr[j + 1];
        float n0 = __int_as_float(e0.y);
        float n1 = __int_as_float(e1.y);
        float4 v0 = h4[(size_t)e0.x * 32 + lane];
        float4 v1 = h4[(size_t)e1.x * 32 + lane];
        acc.x += v0.x * n0 + v1.x * n1;
        acc.y += v0.y * n0 + v1.y * n1;
        acc.z += v0.z * n0 + v1.z * n1;
        acc.w += v0.w * n0 + v1.w * n1;
    }
    if (j < end) {
        int2 e = g_csr[j];
        float nrm = __int_as_float(e.y);
        float4 v = h4[(size_t)e.x * 32 + lane];
        acc.x += v.x * nrm; acc.y += v.y * nrm;
        acc.z += v.z * nrm; acc.w += v.w * nrm;
    }

    float d = g_dinv[node];
    float d2 = d * d;
    float4 hv = h4[(size_t)node * 32 + lane];
    float4 b = bias[lane];
    float4 v = make_float4(acc.x + hv.x * d2 + b.x,
                           acc.y + hv.y * d2 + b.y,
                           acc.z + hv.z * d2 + b.z,
                           acc.w + hv.w * d2 + b.w);
    if (do_relu) {
        v.x = fmaxf(v.x, 0.f); v.y = fmaxf(v.y, 0.f);
        v.z = fmaxf(v.z, 0.f); v.w = fmaxf(v.w, 0.f);
    }
    float4* dst4 = to_act ? (float4*)g_act : out;
    dst4[(size_t)node * 32 + lane] = v;
}

// ---------------- host orchestration ----------------

static void run_graph(const float* x, const void* ei, int n, int E,
                      const float* W0, const float* b0,
                      const float* W1, const float* b1,
                      float* out)
{
    const int TPB = 256;
    int gemm_blocks = (n + 127) / 128;
    int node_blocks = (n + TPB - 1) / TPB;
    int edge_blocks = (E + TPB - 1) / TPB;
    int warp_blocks = (n * 32 + TPB - 1) / TPB;
    int scan_blocks = (n + SCAN_B - 1) / SCAN_B;

    // ---- CSR build (once per graph, reused by both layers) ----
    detect_kernel<<<1, 1>>>((const long long*)ei, E, n);
    zero_cnt_kernel<<<node_blocks, TPB>>>(n);
    count_kernel<<<edge_blocks, TPB>>>(ei, E);
    dinv_kernel<<<node_blocks, TPB>>>(n);
    scan_block_kernel<<<scan_blocks, SCAN_B>>>(n);
    scan_top_kernel<<<1, 256>>>(scan_blocks, n, E);
    scan_add_kernel<<<node_blocks, TPB>>>(n);
    zero_cnt_kernel<<<node_blocks, TPB>>>(n);
    fill_kernel<<<edge_blocks, TPB>>>(ei, E);

    // ---- layer 0 ----
    gemm_tc_kernel<<<gemm_blocks, TPB>>>(x, W0, n, 0);
    gather_kernel<<<warp_blocks, TPB>>>((const float4*)b0, nullptr, n, 1, 1);

    // ---- layer 1 ----
    gemm_tc_kernel<<<gemm_blocks, TPB>>>(nullptr, W1, n, 1);
    gather_kernel<<<warp_blocks, TPB>>>((const float4*)b1, (float4*)out, n, 0, 0);
}

extern "C" void kernel_launch(void* const* d_in, const int* in_sizes, int n_in,
                              void* d_out, int out_size)
{
    const float* x1  = (const float*)d_in[0];
    const void*  ei1 = d_in[1];
    const float* x2  = (const float*)d_in[2];
    const void*  ei2 = d_in[3];
    const float* W0  = (const float*)d_in[4];
    const float* b0  = (const float*)d_in[5];
    const float* W1  = (const float*)d_in[6];
    const float* b1  = (const float*)d_in[7];
    float* out = (float*)d_out;

    int n  = in_sizes[0] / DH;      // 100000
    int E1 = in_sizes[1] / 2;       // 1600000
    int E2 = in_sizes[3] / 2;

    run_graph(x1, ei1, n, E1, W0, b0, W1, b1, out);
    run_graph(x2, ei2, n, E2, W0, b0, W1, b1, out + (size_t)n * DH);
}

// round 6
// speedup vs baseline: 4.4674x; 1.0474x over previous
#include <cuda_runtime.h>
#include <cuda_fp16.h>
#include <cstdint>

#define NMAX 100000
#define EMAX 1600000
#define DH   128
#define SCAN_B 1024
#define XS 36    // sX row stride (floats), padded: conflict-free A-fragment LDS
#define WS 132   // sW row stride (floats), padded: conflict-free B-fragment LDS

// ---------------- scratch (device globals; no allocs allowed) ----------------
__device__ __half g_hh[(size_t)NMAX * DH];   // GEMM output, fp16 (gather input)
__device__ float  g_act[(size_t)NMAX * DH];  // layer-0 activations, fp32
__device__ float  g_dinv[NMAX];
__device__ int    g_cnt[NMAX];               // degree histogram, then scatter cursor
__device__ int    g_rowptr[NMAX + 1];
__device__ int2   g_csr[EMAX];               // {src, float bits of norm}, dst-sorted
__device__ int    g_bsum[256];               // scan block sums
__device__ int    g_is64;

// ---------------- index dtype detection ----------------
// Reference declares int64 edge_index, but JAX silently downcasts to int32
// unless x64 is enabled. Probe the first words read as int64.
__global__ void detect_kernel(const long long* __restrict__ ei, int E, int n) {
    if (threadIdx.x == 0 && blockIdx.x == 0) {
        int probes = E < 64 ? E : 64;
        int is64 = 1;
        for (int i = 0; i < probes; i++) {
            long long v = ei[i];
            if (v < 0 || v >= (long long)n) { is64 = 0; break; }
        }
        g_is64 = is64;
    }
}

__device__ __forceinline__ int load_src(const void* ei, int E, int e) {
    return g_is64 ? (int)((const long long*)ei)[e] : ((const int*)ei)[e];
}
__device__ __forceinline__ int load_dst(const void* ei, int E, int e) {
    return g_is64 ? (int)((const long long*)ei)[(size_t)E + e]
                  : ((const int*)ei)[(size_t)E + e];
}

// ---------------- CSR build ----------------

__global__ void zero_cnt_kernel(int n) {
    int i = blockIdx.x * blockDim.x + threadIdx.x;
    if (i < n) g_cnt[i] = 0;
}

__global__ void count_kernel(const void* __restrict__ ei, int E) {
    int e = blockIdx.x * blockDim.x + threadIdx.x;
    if (e >= E) return;
    atomicAdd(&g_cnt[load_dst(ei, E, e)], 1);
}

__global__ void dinv_kernel(int n) {
    int i = blockIdx.x * blockDim.x + threadIdx.x;
    if (i < n) g_dinv[i] = rsqrtf((float)g_cnt[i] + 1.0f);
}

// exclusive scan of g_cnt into g_rowptr, two-level
__global__ void scan_block_kernel(int n) {
    __shared__ int s[SCAN_B];
    int gid = blockIdx.x * SCAN_B + threadIdx.x;
    int v = (gid < n) ? g_cnt[gid] : 0;
    s[threadIdx.x] = v;
    __syncthreads();
#pragma unroll
    for (int off = 1; off < SCAN_B; off <<= 1) {
        int t = (threadIdx.x >= off) ? s[threadIdx.x - off] : 0;
        __syncthreads();
        s[threadIdx.x] += t;
        __syncthreads();
    }
    if (gid < n) g_rowptr[gid] = s[threadIdx.x] - v;   // exclusive
    if (threadIdx.x == SCAN_B - 1) g_bsum[blockIdx.x] = s[SCAN_B - 1];
}

__global__ void scan_top_kernel(int nb, int n, int E) {
    __shared__ int s[256];
    int v = (threadIdx.x < nb) ? g_bsum[threadIdx.x] : 0;
    s[threadIdx.x] = v;
    __syncthreads();
#pragma unroll
    for (int off = 1; off < 256; off <<= 1) {
        int t = (threadIdx.x >= off) ? s[threadIdx.x - off] : 0;
        __syncthreads();
        s[threadIdx.x] += t;
        __syncthreads();
    }
    if (threadIdx.x < nb) g_bsum[threadIdx.x] = s[threadIdx.x] - v;  // exclusive
    if (threadIdx.x == 0) g_rowptr[n] = E;
}

// add block offsets AND reset g_cnt to zero (cursor for fill)
__global__ void scan_add_kernel(int n) {
    int gid = blockIdx.x * blockDim.x + threadIdx.x;
    if (gid < n) {
        g_rowptr[gid] += g_bsum[gid / SCAN_B];
        g_cnt[gid] = 0;
    }
}

__global__ void fill_kernel(const void* __restrict__ ei, int E) {
    int e = blockIdx.x * blockDim.x + threadIdx.x;
    if (e >= E) return;
    int src = load_src(ei, E, e);
    int dst = load_dst(ei, E, e);
    int pos = g_rowptr[dst] + atomicAdd(&g_cnt[dst], 1);
    float norm = g_dinv[src] * g_dinv[dst];
    g_csr[pos] = make_int2(src, __float_as_int(norm));
}

// ---------------- tensor-core TF32 GEMM ----------------
// g_hh[N,128] = fp16( x[N,128] @ W[128,128] )
// 128 rows/block, 8 warps; warp tile 32x64 = 2x8 m16n8k8 tiles; K chunked x32.
// fp32 -> tf32 conversion at the global->smem copy; fp32 accum; fp16 store.

__device__ __forceinline__ uint32_t f2tf(float f) {
    uint32_t u;
    asm("cvt.rna.tf32.f32 %0, %1;" : "=r"(u) : "f"(f));
    return u;
}

__global__ __launch_bounds__(256) void gemm_tc_kernel(
    const float* __restrict__ x, const float* __restrict__ W,
    int nrows, int use_act)
{
    __shared__ uint32_t sX[128 * XS];   // 18432 B
    __shared__ uint32_t sW[32 * WS];    // 16896 B

    int tid = threadIdx.x;
    int lane = tid & 31;
    int w = tid >> 5;
    int row0 = blockIdx.x * 128;
    int mrow0 = (w & 3) * 32;
    int ncol0 = (w >> 2) * 64;
    int gi = lane >> 2;   // groupID
    int ti = lane & 3;    // thread-in-group

    const float4* xp4 = use_act ? (const float4*)g_act : (const float4*)x;
    const float4* W4 = (const float4*)W;

    float c[2][8][4];
#pragma unroll
    for (int m = 0; m < 2; m++)
#pragma unroll
        for (int nt = 0; nt < 8; nt++)
#pragma unroll
            for (int i = 0; i < 4; i++) c[m][nt][i] = 0.f;

    for (int kc = 0; kc < 4; kc++) {
        __syncthreads();
        // x tile: rows row0..+127, cols kc*32..+31  (1024 float4, 4/thread)
#pragma unroll
        for (int i = 0; i < 4; i++) {
            int idx = tid + i * 256;
            int r = idx >> 3, c4 = idx & 7;
            float4 v = (row0 + r < nrows)
                ? xp4[(size_t)(row0 + r) * 32 + kc * 8 + c4]
                : make_float4(0.f, 0.f, 0.f, 0.f);
            uint32_t* d = &sX[r * XS + c4 * 4];
            d[0] = f2tf(v.x); d[1] = f2tf(v.y); d[2] = f2tf(v.z); d[3] = f2tf(v.w);
        }
        // W tile: rows kc*32..+31, all 128 cols  (1024 float4, 4/thread)
#pragma unroll
        for (int i = 0; i < 4; i++) {
            int idx = tid + i * 256;
            int r = idx >> 5, c4 = idx & 31;
            float4 v = W4[(size_t)(kc * 32 + r) * 32 + c4];
            uint32_t* d = &sW[r * WS + c4 * 4];
            d[0] = f2tf(v.x); d[1] = f2tf(v.y); d[2] = f2tf(v.z); d[3] = f2tf(v.w);
        }
        __syncthreads();

#pragma unroll
        for (int kk = 0; kk < 4; kk++) {
            int kcol = kk * 8;
            uint32_t a[2][4];
#pragma unroll
            for (int m = 0; m < 2; m++) {
                int rb = mrow0 + m * 16 + gi;
                a[m][0] = sX[rb * XS + kcol + ti];
                a[m][1] = sX[(rb + 8) * XS + kcol + ti];
                a[m][2] = sX[rb * XS + kcol + ti + 4];
                a[m][3] = sX[(rb + 8) * XS + kcol + ti + 4];
            }
#pragma unroll
            for (int nt = 0; nt < 8; nt++) {
                int n0 = ncol0 + nt * 8 + gi;
                uint32_t b0 = sW[(kcol + ti) * WS + n0];
                uint32_t b1 = sW[(kcol + ti + 4) * WS + n0];
#pragma unroll
                for (int m = 0; m < 2; m++) {
                    asm volatile(
                        "mma.sync.aligned.m16n8k8.row.col.f32.tf32.tf32.f32 "
                        "{%0,%1,%2,%3}, {%4,%5,%6,%7}, {%8,%9}, {%0,%1,%2,%3};"
                        : "+f"(c[m][nt][0]), "+f"(c[m][nt][1]),
                          "+f"(c[m][nt][2]), "+f"(c[m][nt][3])
                        : "r"(a[m][0]), "r"(a[m][1]), "r"(a[m][2]), "r"(a[m][3]),
                          "r"(b0), "r"(b1));
                }
            }
        }
    }

    // epilogue: fp16 store. c0/c1 -> row gi, cols 2ti..2ti+1 ; c2/c3 -> row gi+8
#pragma unroll
    for (int m = 0; m < 2; m++) {
        int r0 = row0 + mrow0 + m * 16 + gi;
#pragma unroll
        for (int nt = 0; nt < 8; nt++) {
            int col = ncol0 + nt * 8 + 2 * ti;
            if (r0 < nrows)
                *(__half2*)&g_hh[(size_t)r0 * DH + col] =
                    __floats2half2_rn(c[m][nt][0], c[m][nt][1]);
            if (r0 + 8 < nrows)
                *(__half2*)&g_hh[(size_t)(r0 + 8) * DH + col] =
                    __floats2half2_rn(c[m][nt][2], c[m][nt][3]);
        }
    }
}

// ---------------- fused gather + combine ----------------
// One warp per dst node. Lane owns 4 feature dims (one uint2 = 4 halves).
// Accumulates in-edges in fp32 from fp16 h (CSR gather, no atomics), adds
// self-loop + bias, optional ReLU, writes result once.
__global__ void gather_kernel(const float4* __restrict__ bias,
                              float4* __restrict__ out, int n,
                              int do_relu, int to_act)
{
    int t = blockIdx.x * blockDim.x + threadIdx.x;
    int node = t >> 5;
    if (node >= n) return;
    int lane = t & 31;

    int beg = g_rowptr[node];
    int end = g_rowptr[node + 1];

    const uint2* hh2 = (const uint2*)g_hh;   // 32 uint2 per row (128 halves)
    float4 acc = make_float4(0.f, 0.f, 0.f, 0.f);

    int j = beg;
    for (; j + 1 < end; j += 2) {
        int2 e0 = g_csr[j];
        int2 e1 = g_csr[j + 1];
        float n0 = __int_as_float(e0.y);
        float n1 = __int_as_float(e1.y);
        uint2 r0 = hh2[(size_t)e0.x * 32 + lane];
        uint2 r1 = hh2[(size_t)e1.x * 32 + lane];
        float2 a0 = __half22float2(*(__half2*)&r0.x);
        float2 a1 = __half22float2(*(__half2*)&r0.y);
        float2 b0 = __half22float2(*(__half2*)&r1.x);
        float2 b1 = __half22float2(*(__half2*)&r1.y);
        acc.x += a0.x * n0 + b0.x * n1;
        acc.y += a0.y * n0 + b0.y * n1;
        acc.z += a1.x * n0 + b1.x * n1;
        acc.w += a1.y * n0 + b1.y * n1;
    }
    if (j < end) {
        int2 e = g_csr[j];
        float nrm = __int_as_float(e.y);
        uint2 r0 = hh2[(size_t)e.x * 32 + lane];
        float2 a0 = __half22float2(*(__half2*)&r0.x);
        float2 a1 = __half22float2(*(__half2*)&r0.y);
        acc.x += a0.x * nrm;
        acc.y += a0.y * nrm;
        acc.z += a1.x * nrm;
        acc.w += a1.y * nrm;
    }

    float d = g_dinv[node];
    float d2 = d * d;
    uint2 rs = hh2[(size_t)node * 32 + lane];
    float2 s0 = __half22float2(*(__half2*)&rs.x);
    float2 s1 = __half22float2(*(__half2*)&rs.y);
    float4 b = bias[lane];
    float4 v = make_float4(acc.x + s0.x * d2 + b.x,
                           acc.y + s0.y * d2 + b.y,
                           acc.z + s1.x * d2 + b.z,
                           acc.w + s1.y * d2 + b.w);
    if (do_relu) {
        v.x = fmaxf(v.x, 0.f); v.y = fmaxf(v.y, 0.f);
        v.z = fmaxf(v.z, 0.f); v.w = fmaxf(v.w, 0.f);
    }
    float4* dst4 = to_act ? (float4*)g_act : out;
    dst4[(size_t)node * 32 + lane] = v;
}

// ---------------- host orchestration ----------------

static void run_graph(const float* x, const void* ei, int n, int E,
                      const float* W0, const float* b0,
                      const float* W1, const float* b1,
                      float* out)
{
    const int TPB = 256;
    int gemm_blocks = (n + 127) / 128;
    int node_blocks = (n + TPB - 1) / TPB;
    int edge_blocks = (E + TPB - 1) / TPB;
    int warp_blocks = (n * 32 + TPB - 1) / TPB;
    int scan_blocks = (n + SCAN_B - 1) / SCAN_B;

    // ---- CSR build (once per graph, reused by both layers) ----
    detect_kernel<<<1, 1>>>((const long long*)ei, E, n);
    zero_cnt_kernel<<<node_blocks, TPB>>>(n);
    count_kernel<<<edge_blocks, TPB>>>(ei, E);
    dinv_kernel<<<node_blocks, TPB>>>(n);
    scan_block_kernel<<<scan_blocks, SCAN_B>>>(n);
    scan_top_kernel<<<1, 256>>>(scan_blocks, n, E);
    scan_add_kernel<<<node_blocks, TPB>>>(n);   // also zeroes g_cnt (cursor)
    fill_kernel<<<edge_blocks, TPB>>>(ei, E);

    // ---- layer 0 ----
    gemm_tc_kernel<<<gemm_blocks, TPB>>>(x, W0, n, 0);
    gather_kernel<<<warp_blocks, TPB>>>((const float4*)b0, nullptr, n, 1, 1);

    // ---- layer 1 ----
    gemm_tc_kernel<<<gemm_blocks, TPB>>>(nullptr, W1, n, 1);
    gather_kernel<<<warp_blocks, TPB>>>((const float4*)b1, (float4*)out, n, 0, 0);
}

extern "C" void kernel_launch(void* const* d_in, const int* in_sizes, int n_in,
                              void* d_out, int out_size)
{
    const float* x1  = (const float*)d_in[0];
    const void*  ei1 = d_in[1];
    const float* x2  = (const float*)d_in[2];
    const void*  ei2 = d_in[3];
    const float* W0  = (const float*)d_in[4];
    const float* b0  = (const float*)d_in[5];
    const float* W1  = (const float*)d_in[6];
    const float* b1  = (const float*)d_in[7];
    float* out = (float*)d_out;

    int n  = in_sizes[0] / DH;      // 100000
    int E1 = in_sizes[1] / 2;       // 1600000
    int E2 = in_sizes[3] / 2;

    run_graph(x1, ei1, n, E1, W0, b0, W1, b1, out);
    run_graph(x2, ei2, n, E2, W0, b0, W1, b1, out + (size_t)n * DH);
}

// round 7
// speedup vs baseline: 4.6743x; 1.0463x over previous
#include <cuda_runtime.h>
#include <cuda_fp16.h>
#include <cstdint>

#define NMAX 100000
#define EMAX 1600000
#define DH   128
#define SCAN_B 1024
#define XS 36    // sX row stride (floats), padded: conflict-free A-fragment LDS
#define WS 132   // sW row stride (floats), padded: conflict-free B-fragment LDS

// ---------------- scratch (device globals; no allocs allowed) -------------
// All scratch is [2]-indexed so the two independent graphs can run on
// overlapping streams without aliasing.
__device__ __half g_hh[2][(size_t)NMAX * DH];   // GEMM out, fp16 (gather input)
__device__ __half g_act[2][(size_t)NMAX * DH];  // layer-0 activations, fp16
__device__ float  g_dinv[2][NMAX];
__device__ int    g_cnt[2][NMAX];               // histogram, then scatter cursor
__device__ int    g_rowptr[2][NMAX + 1];
__device__ int2   g_csr[2][EMAX];               // {src, bits(norm)}, dst-sorted
__device__ int    g_bsum[2][256];               // scan block sums
__device__ int    g_is64[2];

// ---------------- index dtype detection ----------------
// Reference declares int64 edge_index, but JAX silently downcasts to int32
// unless x64 is enabled. Probe the first words read as int64.
__global__ void detect_kernel(const long long* __restrict__ ei, int E, int n, int gid) {
    if (threadIdx.x == 0 && blockIdx.x == 0) {
        int probes = E < 64 ? E : 64;
        int is64 = 1;
        for (int i = 0; i < probes; i++) {
            long long v = ei[i];
            if (v < 0 || v >= (long long)n) { is64 = 0; break; }
        }
        g_is64[gid] = is64;
    }
}

__device__ __forceinline__ int load_src(const void* ei, int E, int e, int gid) {
    return g_is64[gid] ? (int)((const long long*)ei)[e] : ((const int*)ei)[e];
}
__device__ __forceinline__ int load_dst(const void* ei, int E, int e, int gid) {
    return g_is64[gid] ? (int)((const long long*)ei)[(size_t)E + e]
                       : ((const int*)ei)[(size_t)E + e];
}

// ---------------- CSR build ----------------

__global__ void zero_cnt_kernel(int n, int gid) {
    int i = blockIdx.x * blockDim.x + threadIdx.x;
    if (i < n) g_cnt[gid][i] = 0;
}

__global__ void count_kernel(const void* __restrict__ ei, int E, int gid) {
    int e = blockIdx.x * blockDim.x + threadIdx.x;
    if (e >= E) return;
    atomicAdd(&g_cnt[gid][load_dst(ei, E, e, gid)], 1);
}

// exclusive scan of g_cnt into g_rowptr (two-level); also emits dinv.
__global__ void scan_block_kernel(int n, int gid) {
    __shared__ int s[SCAN_B];
    int gidx = blockIdx.x * SCAN_B + threadIdx.x;
    int v = (gidx < n) ? g_cnt[gid][gidx] : 0;
    if (gidx < n) g_dinv[gid][gidx] = rsqrtf((float)v + 1.0f);
    s[threadIdx.x] = v;
    __syncthreads();
#pragma unroll
    for (int off = 1; off < SCAN_B; off <<= 1) {
        int t = (threadIdx.x >= off) ? s[threadIdx.x - off] : 0;
        __syncthreads();
        s[threadIdx.x] += t;
        __syncthreads();
    }
    if (gidx < n) g_rowptr[gid][gidx] = s[threadIdx.x] - v;   // exclusive
    if (threadIdx.x == SCAN_B - 1) g_bsum[gid][blockIdx.x] = s[SCAN_B - 1];
}

__global__ void scan_top_kernel(int nb, int n, int E, int gid) {
    __shared__ int s[256];
    int v = (threadIdx.x < nb) ? g_bsum[gid][threadIdx.x] : 0;
    s[threadIdx.x] = v;
    __syncthreads();
#pragma unroll
    for (int off = 1; off < 256; off <<= 1) {
        int t = (threadIdx.x >= off) ? s[threadIdx.x - off] : 0;
        __syncthreads();
        s[threadIdx.x] += t;
        __syncthreads();
    }
    if (threadIdx.x < nb) g_bsum[gid][threadIdx.x] = s[threadIdx.x] - v;  // exclusive
    if (threadIdx.x == 0) g_rowptr[gid][n] = E;
}

// add block offsets AND reset g_cnt to zero (cursor for fill)
__global__ void scan_add_kernel(int n, int gid) {
    int gidx = blockIdx.x * blockDim.x + threadIdx.x;
    if (gidx < n) {
        g_rowptr[gid][gidx] += g_bsum[gid][gidx / SCAN_B];
        g_cnt[gid][gidx] = 0;
    }
}

__global__ void fill_kernel(const void* __restrict__ ei, int E, int gid) {
    int e = blockIdx.x * blockDim.x + threadIdx.x;
    if (e >= E) return;
    int src = load_src(ei, E, e, gid);
    int dst = load_dst(ei, E, e, gid);
    int pos = g_rowptr[gid][dst] + atomicAdd(&g_cnt[gid][dst], 1);
    float norm = g_dinv[gid][src] * g_dinv[gid][dst];
    g_csr[gid][pos] = make_int2(src, __float_as_int(norm));
}

// ---------------- tensor-core TF32 GEMM ----------------
// g_hh[gid][N,128] = fp16( X[N,128] @ W[128,128] ), X fp32 (layer0 input) or
// fp16 (g_act, layer1). 128 rows/block, 8 warps; warp tile 32x64 = 2x8
// m16n8k8 tiles; K chunked x32. fp32 accumulate, fp16 store.

__device__ __forceinline__ uint32_t f2tf(float f) {
    uint32_t u;
    asm("cvt.rna.tf32.f32 %0, %1;" : "=r"(u) : "f"(f));
    return u;
}

__global__ __launch_bounds__(256) void gemm_tc_kernel(
    const float* __restrict__ xf, const float* __restrict__ W,
    int nrows, int in_half, int gid)
{
    __shared__ uint32_t sX[128 * XS];   // 18432 B
    __shared__ uint32_t sW[32 * WS];    // 16896 B

    int tid = threadIdx.x;
    int lane = tid & 31;
    int w = tid >> 5;
    int row0 = blockIdx.x * 128;
    int mrow0 = (w & 3) * 32;
    int ncol0 = (w >> 2) * 64;
    int gi = lane >> 2;   // groupID
    int ti = lane & 3;    // thread-in-group

    const float4* xp4 = (const float4*)xf;
    const uint2*  xh2 = (const uint2*)g_act[gid];
    const float4* W4 = (const float4*)W;

    float c[2][8][4];
#pragma unroll
    for (int m = 0; m < 2; m++)
#pragma unroll
        for (int nt = 0; nt < 8; nt++)
#pragma unroll
            for (int i = 0; i < 4; i++) c[m][nt][i] = 0.f;

    for (int kc = 0; kc < 4; kc++) {
        __syncthreads();
        // x tile: rows row0..+127, cols kc*32..+31  (1024 groups of 4 elems)
#pragma unroll
        for (int i = 0; i < 4; i++) {
            int idx = tid + i * 256;
            int r = idx >> 3, c4 = idx & 7;
            float4 v;
            if (row0 + r < nrows) {
                if (in_half) {
                    uint2 u = xh2[(size_t)(row0 + r) * 32 + kc * 8 + c4];
                    float2 p0 = __half22float2(*(__half2*)&u.x);
                    float2 p1 = __half22float2(*(__half2*)&u.y);
                    v = make_float4(p0.x, p0.y, p1.x, p1.y);
                } else {
                    v = xp4[(size_t)(row0 + r) * 32 + kc * 8 + c4];
                }
            } else v = make_float4(0.f, 0.f, 0.f, 0.f);
            uint32_t* d = &sX[r * XS + c4 * 4];
            d[0] = f2tf(v.x); d[1] = f2tf(v.y); d[2] = f2tf(v.z); d[3] = f2tf(v.w);
        }
        // W tile: rows kc*32..+31, all 128 cols  (1024 float4, 4/thread)
#pragma unroll
        for (int i = 0; i < 4; i++) {
            int idx = tid + i * 256;
            int r = idx >> 5, c4 = idx & 31;
            float4 v = W4[(size_t)(kc * 32 + r) * 32 + c4];
            uint32_t* d = &sW[r * WS + c4 * 4];
            d[0] = f2tf(v.x); d[1] = f2tf(v.y); d[2] = f2tf(v.z); d[3] = f2tf(v.w);
        }
        __syncthreads();

#pragma unroll
        for (int kk = 0; kk < 4; kk++) {
            int kcol = kk * 8;
            uint32_t a[2][4];
#pragma unroll
            for (int m = 0; m < 2; m++) {
                int rb = mrow0 + m * 16 + gi;
                a[m][0] = sX[rb * XS + kcol + ti];
                a[m][1] = sX[(rb + 8) * XS + kcol + ti];
                a[m][2] = sX[rb * XS + kcol + ti + 4];
                a[m][3] = sX[(rb + 8) * XS + kcol + ti + 4];
            }
#pragma unroll
            for (int nt = 0; nt < 8; nt++) {
                int n0 = ncol0 + nt * 8 + gi;
                uint32_t b0 = sW[(kcol + ti) * WS + n0];
                uint32_t b1 = sW[(kcol + ti + 4) * WS + n0];
#pragma unroll
                for (int m = 0; m < 2; m++) {
                    asm volatile(
                        "mma.sync.aligned.m16n8k8.row.col.f32.tf32.tf32.f32 "
                        "{%0,%1,%2,%3}, {%4,%5,%6,%7}, {%8,%9}, {%0,%1,%2,%3};"
                        : "+f"(c[m][nt][0]), "+f"(c[m][nt][1]),
                          "+f"(c[m][nt][2]), "+f"(c[m][nt][3])
                        : "r"(a[m][0]), "r"(a[m][1]), "r"(a[m][2]), "r"(a[m][3]),
                          "r"(b0), "r"(b1));
                }
            }
        }
    }

    // epilogue: fp16 store. c0/c1 -> row gi, cols 2ti..+1 ; c2/c3 -> row gi+8
    __half* hh = g_hh[gid];
#pragma unroll
    for (int m = 0; m < 2; m++) {
        int r0 = row0 + mrow0 + m * 16 + gi;
#pragma unroll
        for (int nt = 0; nt < 8; nt++) {
            int col = ncol0 + nt * 8 + 2 * ti;
            if (r0 < nrows)
                *(__half2*)&hh[(size_t)r0 * DH + col] =
                    __floats2half2_rn(c[m][nt][0], c[m][nt][1]);
            if (r0 + 8 < nrows)
                *(__half2*)&hh[(size_t)(r0 + 8) * DH + col] =
                    __floats2half2_rn(c[m][nt][2], c[m][nt][3]);
        }
    }
}

// ---------------- fused gather + combine ----------------
// One warp per dst node. Lane owns 4 feature dims (one uint2 = 4 halves).
// fp32 accumulation over fp16 h; adds self-loop + bias, optional ReLU.
// Writes fp16 g_act (to_act) or fp32 out.
__global__ void gather_kernel(const float4* __restrict__ bias,
                              float4* __restrict__ out, int n,
                              int do_relu, int to_act, int gid)
{
    int t = blockIdx.x * blockDim.x + threadIdx.x;
    int node = t >> 5;
    if (node >= n) return;
    int lane = t & 31;

    int beg = g_rowptr[gid][node];
    int end = g_rowptr[gid][node + 1];

    const uint2* hh2 = (const uint2*)g_hh[gid];   // 32 uint2 per row
    const int2* csr = g_csr[gid];
    float4 acc = make_float4(0.f, 0.f, 0.f, 0.f);

    int j = beg;
    for (; j + 1 < end; j += 2) {
        int2 e0 = csr[j];
        int2 e1 = csr[j + 1];
        float n0 = __int_as_float(e0.y);
        float n1 = __int_as_float(e1.y);
        uint2 r0 = hh2[(size_t)e0.x * 32 + lane];
        uint2 r1 = hh2[(size_t)e1.x * 32 + lane];
        float2 a0 = __half22float2(*(__half2*)&r0.x);
        float2 a1 = __half22float2(*(__half2*)&r0.y);
        float2 b0 = __half22float2(*(__half2*)&r1.x);
        float2 b1 = __half22float2(*(__half2*)&r1.y);
        acc.x += a0.x * n0 + b0.x * n1;
        acc.y += a0.y * n0 + b0.y * n1;
        acc.z += a1.x * n0 + b1.x * n1;
        acc.w += a1.y * n0 + b1.y * n1;
    }
    if (j < end) {
        int2 e = csr[j];
        float nrm = __int_as_float(e.y);
        uint2 r0 = hh2[(size_t)e.x * 32 + lane];
        float2 a0 = __half22float2(*(__half2*)&r0.x);
        float2 a1 = __half22float2(*(__half2*)&r0.y);
        acc.x += a0.x * nrm;
        acc.y += a0.y * nrm;
        acc.z += a1.x * nrm;
        acc.w += a1.y * nrm;
    }

    float d = g_dinv[gid][node];
    float d2 = d * d;
    uint2 rs = hh2[(size_t)node * 32 + lane];
    float2 s0 = __half22float2(*(__half2*)&rs.x);
    float2 s1 = __half22float2(*(__half2*)&rs.y);
    float4 b = bias[lane];
    float4 v = make_float4(acc.x + s0.x * d2 + b.x,
                           acc.y + s0.y * d2 + b.y,
                           acc.z + s1.x * d2 + b.z,
                           acc.w + s1.y * d2 + b.w);
    if (do_relu) {
        v.x = fmaxf(v.x, 0.f); v.y = fmaxf(v.y, 0.f);
        v.z = fmaxf(v.z, 0.f); v.w = fmaxf(v.w, 0.f);
    }
    if (to_act) {
        __half2 h0 = __floats2half2_rn(v.x, v.y);
        __half2 h1 = __floats2half2_rn(v.z, v.w);
        uint2 u;
        u.x = *(uint32_t*)&h0;
        u.y = *(uint32_t*)&h1;
        ((uint2*)g_act[gid])[(size_t)node * 32 + lane] = u;
    } else {
        out[(size_t)node * 32 + lane] = v;
    }
}

// ---------------- host orchestration ----------------

static void run_graph(const float* x, const void* ei, int n, int E,
                      const float* W0, const float* b0,
                      const float* W1, const float* b1,
                      float* out, int gid, cudaStream_t st)
{
    const int TPB = 256;
    int gemm_blocks = (n + 127) / 128;
    int node_blocks = (n + TPB - 1) / TPB;
    int edge_blocks = (E + TPB - 1) / TPB;
    int warp_blocks = (n * 32 + TPB - 1) / TPB;
    int scan_blocks = (n + SCAN_B - 1) / SCAN_B;

    // ---- CSR build (once per graph, reused by both layers) ----
    detect_kernel<<<1, 1, 0, st>>>((const long long*)ei, E, n, gid);
    zero_cnt_kernel<<<node_blocks, TPB, 0, st>>>(n, gid);
    count_kernel<<<edge_blocks, TPB, 0, st>>>(ei, E, gid);
    scan_block_kernel<<<scan_blocks, SCAN_B, 0, st>>>(n, gid);  // also emits dinv
    scan_top_kernel<<<1, 256, 0, st>>>(scan_blocks, n, E, gid);
    scan_add_kernel<<<node_blocks, TPB, 0, st>>>(n, gid);       // also zeroes cnt
    fill_kernel<<<edge_blocks, TPB, 0, st>>>(ei, E, gid);

    // ---- layer 0 ----
    gemm_tc_kernel<<<gemm_blocks, TPB, 0, st>>>(x, W0, n, 0, gid);
    gather_kernel<<<warp_blocks, TPB, 0, st>>>((const float4*)b0, nullptr, n, 1, 1, gid);

    // ---- layer 1 ----
    gemm_tc_kernel<<<gemm_blocks, TPB, 0, st>>>(nullptr, W1, n, 1, gid);
    gather_kernel<<<warp_blocks, TPB, 0, st>>>((const float4*)b1, (float4*)out, n, 0, 0, gid);
}

extern "C" void kernel_launch(void* const* d_in, const int* in_sizes, int n_in,
                              void* d_out, int out_size)
{
    const float* x1  = (const float*)d_in[0];
    const void*  ei1 = d_in[1];
    const float* x2  = (const float*)d_in[2];
    const void*  ei2 = d_in[3];
    const float* W0  = (const float*)d_in[4];
    const float* b0  = (const float*)d_in[5];
    const float* W1  = (const float*)d_in[6];
    const float* b1  = (const float*)d_in[7];
    float* out = (float*)d_out;

    int n  = in_sizes[0] / DH;      // 100000
    int E1 = in_sizes[1] / 2;       // 1600000
    int E2 = in_sizes[3] / 2;

    // Fork a second stream so the two independent graphs overlap (captured as
    // a branched CUDA graph). Host objects only — no device allocation.
    // kernel_launch runs only a handful of times (correctness + capture), so
    // creating (and not destroying, to stay capture-safe) is harmless.
    cudaStream_t s2 = 0;
    cudaEvent_t evFork = 0, evJoin = 0;
    bool forked =
        cudaStreamCreateWithFlags(&s2, cudaStreamNonBlocking) == cudaSuccess &&
        cudaEventCreateWithFlags(&evFork, cudaEventDisableTiming) == cudaSuccess &&
        cudaEventCreateWithFlags(&evJoin, cudaEventDisableTiming) == cudaSuccess;

    if (forked) {
        cudaEventRecord(evFork, 0);
        cudaStreamWaitEvent(s2, evFork, 0);
    }

    run_graph(x1, ei1, n, E1, W0, b0, W1, b1, out, 0, 0);
    run_graph(x2, ei2, n, E2, W0, b0, W1, b1, out + (size_t)n * DH, 1,
              forked ? s2 : 0);

    if (forked) {
        cudaEventRecord(evJoin, s2);
        cudaStreamWaitEvent(0, evJoin, 0);
    }
}